// round 1
// baseline (speedup 1.0000x reference)
#include <cuda_runtime.h>

#define Nn   2048      // B*S
#define Bv   16
#define Sv   128
#define Hv   256
#define DINv 256
#define DEv  192
#define DRv  64
#define Ev   2032      // B*(S-1)
#define Lv   12
#define NCTA 128
#define NTHR 256
#define SMEM_BYTES 196608   // 48K floats

// ---------------- device scratch (no allocations allowed) ----------------
__device__ float g_x[Nn * DINv];
__device__ float g_proj[4][Nn * Hv];   // ix(+b_ix+b_ih), fx(+b_fx+b_fh), ox, ux
__device__ float g_h[Nn * Hv];
__device__ float g_c[Nn * Hv];
__device__ int   g_coff[Nn + 1];
__device__ int   g_children[Ev];
__device__ int   g_lvl_off[34];
__device__ int   g_lvl_nodes[Nn];
__device__ int   g_maxlev;
__device__ unsigned g_bar_cnt = 0;
__device__ unsigned g_bar_gen = 0;

// ---------------- software grid barrier (all 128 CTAs resident) ----------
__device__ __forceinline__ void grid_bar() {
    __syncthreads();
    if (threadIdx.x == 0) {
        __threadfence();                       // release my CTA's writes
        volatile unsigned* genp = (volatile unsigned*)&g_bar_gen;
        unsigned gen = *genp;                  // read phase BEFORE arriving
        unsigned t = atomicAdd(&g_bar_cnt, 1u);
        if (t == gridDim.x - 1) {
            g_bar_cnt = 0;
            __threadfence();
            atomicAdd(&g_bar_gen, 1u);         // release
        } else {
            while (*genp == gen) { __nanosleep(32); }
        }
        __threadfence();                       // acquire
    }
    __syncthreads();
}

__device__ __forceinline__ float sigf(float x) {
    return 1.0f / (1.0f + __expf(-x));
}

// ---------------- setup: CSR of children + level buckets (deterministic) --
__global__ void setup_kernel(const int* __restrict__ child_idx,
                             const int* __restrict__ parent_idx,
                             const int* __restrict__ node_height) {
    __shared__ int cnt[Nn];
    __shared__ int psm[Ev];
    __shared__ int hsm[Nn];
    __shared__ int part[256];
    __shared__ int lvl[33];
    const int tid = threadIdx.x;               // 1024 threads
    for (int i = tid; i < Nn; i += 1024) { cnt[i] = 0; hsm[i] = node_height[i]; }
    for (int i = tid; i < Ev; i += 1024) psm[i] = parent_idx[i];
    if (tid < 33) lvl[tid] = 0;
    __syncthreads();
    for (int e = tid; e < Ev; e += 1024) atomicAdd(&cnt[psm[e]], 1);
    for (int n = tid; n < Nn; n += 1024) atomicAdd(&lvl[hsm[n]], 1);
    __syncthreads();
    if (tid < 256) { int s = 0; for (int i = 0; i < 8; i++) s += cnt[tid * 8 + i]; part[tid] = s; }
    __syncthreads();
    if (tid == 0) {
        int run = 0;
        for (int i = 0; i < 256; i++) { int v = part[i]; part[i] = run; run += v; }
        int run2 = 0, maxl = 0;
        for (int l = 0; l < 33; l++) {
            g_lvl_off[l] = run2;
            if (lvl[l] > 0) maxl = l;
            run2 += lvl[l];
        }
        g_lvl_off[33] = run2;
        g_maxlev = maxl;
    }
    __syncthreads();
    if (tid < 256) {
        int run = part[tid];
        for (int i = 0; i < 8; i++) { int idx = tid * 8 + i; g_coff[idx] = run; run += cnt[idx]; }
        if (tid == 255) g_coff[Nn] = run;
    }
    __syncthreads();
    // deterministic CSR scatter: rank = #earlier same-parent edges (same batch only)
    for (int e = tid; e < Ev; e += 1024) {
        int p = psm[e];
        int bstart = (e / (Sv - 1)) * (Sv - 1);
        int rank = 0;
        for (int e2 = bstart; e2 < e; e2++) rank += (psm[e2] == p);
        g_children[g_coff[p] + rank] = child_idx[e];
    }
    // deterministic level scatter: rank = #earlier same-height nodes
    for (int n = tid; n < Nn; n += 1024) {
        int lv = hsm[n];
        int rank = 0;
        for (int n2 = 0; n2 < n; n2++) rank += (hsm[n2] == lv);
        g_lvl_nodes[g_lvl_off[lv] + rank] = n;
    }
}

// ---------------- persistent kernel: everything else ---------------------
__global__ void __launch_bounds__(NTHR, 1)
main_kernel(const int* __restrict__ xs, const int* __restrict__ rels,
            const float* __restrict__ emb_W, const float* __restrict__ rel_W,
            const float* __restrict__ W_ix, const float* __restrict__ b_ix,
            const float* __restrict__ W_ih, const float* __restrict__ b_ih,
            const float* __restrict__ W_fx, const float* __restrict__ b_fx,
            const float* __restrict__ W_fh, const float* __restrict__ b_fh,
            const float* __restrict__ W_ox, const float* __restrict__ W_oh,
            const float* __restrict__ W_ux, const float* __restrict__ W_uh,
            const float* __restrict__ W_out, const float* __restrict__ b_out,
            float* __restrict__ out) {
    extern __shared__ float sm[];
    float* Wx_sh  = sm;              // 8192 floats: input-proj column slice
    float* Wih_sh = sm + 8192;
    float* Woh_sh = sm + 2 * 8192;
    float* Wuh_sh = sm + 3 * 8192;
    float* Wfh_sh = sm + 4 * 8192;
    float* scratch = sm + 5 * 8192;  // 8192 floats, phase-aliased

    const int tid  = threadIdx.x;
    const int lane = tid & 31;
    const int warp = tid >> 5;
    const int blk  = blockIdx.x;
    const int cgr  = blk & 7;        // recurrence column group (32 cols of H)
    const int cgp  = blk & 31;       // prologue column group (32 cols of 4H)

    // ---- P0: smem weight slices + build x = [emb | rel] -----------------
    {
        const float* mats[4] = {W_ix, W_fx, W_ox, W_ux};
        const float* Wsel = mats[cgp >> 3];
        const int jbase = (cgp & 7) * 32;
        const int jb2 = cgr * 32;
        for (int idx = tid; idx < 8192; idx += NTHR) {
            int k = idx >> 5, jl = idx & 31;
            Wx_sh[idx]  = Wsel[k * Hv + jbase + jl];
            Wih_sh[idx] = W_ih[k * Hv + jb2 + jl];
            Woh_sh[idx] = W_oh[k * Hv + jb2 + jl];
            Wuh_sh[idx] = W_uh[k * Hv + jb2 + jl];
            Wfh_sh[idx] = W_fh[k * Hv + jb2 + jl];
        }
        for (int r = 0; r < 16; r++) {
            int row = blk * 16 + r;
            int j = tid;
            float v;
            if (j < DEv) v = emb_W[xs[row] * DEv + j];
            else         v = rel_W[rels[row] * DRv + (j - DEv)];
            g_x[row * DINv + j] = v;
        }
    }
    grid_bar();

    // ---- P1: input projections, biases folded ---------------------------
    {
        const int mat = cgp >> 3;
        const int j = (cgp & 7) * 32 + lane;
        float bias = 0.0f;
        if (mat == 0)      bias = b_ix[j] + b_ih[j];
        else if (mat == 1) bias = b_fx[j] + b_fh[j];
        float* x4 = scratch + warp * 1024;            // 4 nodes x 256, interleaved
        const int slot = (blk >> 5) * 8 + warp;        // 0..31
        float* dst = g_proj[mat];
        for (int t = 0; t < 16; t++) {
            int nb = slot * 64 + t * 4;
            __syncwarp();
            #pragma unroll
            for (int m = 0; m < 4; m++) {
                const float* xr = g_x + (nb + m) * DINv;
                for (int k = lane; k < DINv; k += 32) x4[k * 4 + m] = xr[k];
            }
            __syncwarp();
            float a0 = 0, a1 = 0, a2 = 0, a3 = 0;
            #pragma unroll 4
            for (int k = 0; k < DINv; k++) {
                float w = Wx_sh[k * 32 + lane];
                float4 xv = *(const float4*)&x4[k * 4];
                a0 += xv.x * w; a1 += xv.y * w; a2 += xv.z * w; a3 += xv.w * w;
            }
            dst[(nb + 0) * Hv + j] = a0 + bias;
            dst[(nb + 1) * Hv + j] = a1 + bias;
            dst[(nb + 2) * Hv + j] = a2 + bias;
            dst[(nb + 3) * Hv + j] = a3 + bias;
        }
    }
    grid_bar();

    // ---- P2: level 0 (leaves): pure elementwise -------------------------
    {
        int c0 = g_lvl_off[1];                 // lvl_off[0] == 0
        int tot = c0 * Hv;
        for (int e = blk * NTHR + tid; e < tot; e += NCTA * NTHR) {
            int n = g_lvl_nodes[e >> 8];
            int j = e & 255;
            int idx = n * Hv + j;
            float iv = sigf(g_proj[0][idx]);
            float ov = sigf(g_proj[2][idx]);
            float uv = tanhf(g_proj[3][idx]);
            float cv = iv * uv;
            g_c[idx] = cv;
            g_h[idx] = ov * tanhf(cv);
        }
    }
    grid_bar();

    // ---- P3: bottom-up levels -------------------------------------------
    {
        const int maxlev = g_maxlev;
        float* hb = scratch + warp * 256;
        float* cb = scratch + 2048 + warp * 256;
        const int J = cgr * 32 + lane;
        const int slot = (blk >> 3) * 8 + warp;   // 0..127

        for (int lev = 1; lev <= maxlev; lev++) {
            int base = g_lvl_off[lev];
            int cnt  = g_lvl_off[lev + 1] - base;
            for (int idx = slot; idx < cnt; idx += 128) {
                int n = g_lvl_nodes[base + idx];
                float hr0 = 0, hr1 = 0, hr2 = 0, hr3 = 0, hr4 = 0, hr5 = 0, hr6 = 0, hr7 = 0;
                float fc = 0.0f;
                float fxv = g_proj[1][n * Hv + J];
                int cs = g_coff[n], ce = g_coff[n + 1];
                for (int ci = cs; ci < ce; ci++) {
                    int ch = g_children[ci];
                    __syncwarp();
                    float4 v0 = *(const float4*)&g_h[ch * Hv + lane * 4];
                    float4 v1 = *(const float4*)&g_h[ch * Hv + 128 + lane * 4];
                    *(float4*)&cb[lane * 4] = v0;
                    *(float4*)&cb[128 + lane * 4] = v1;
                    hr0 += v0.x; hr1 += v0.y; hr2 += v0.z; hr3 += v0.w;
                    hr4 += v1.x; hr5 += v1.y; hr6 += v1.z; hr7 += v1.w;
                    __syncwarp();
                    float b0 = 0, b1 = 0, b2 = 0, b3 = 0;
                    #pragma unroll 4
                    for (int k = 0; k < Hv; k += 4) {
                        float4 cv = *(const float4*)&cb[k];
                        b0 += cv.x * Wfh_sh[(k + 0) * 32 + lane];
                        b1 += cv.y * Wfh_sh[(k + 1) * 32 + lane];
                        b2 += cv.z * Wfh_sh[(k + 2) * 32 + lane];
                        b3 += cv.w * Wfh_sh[(k + 3) * 32 + lane];
                    }
                    float f = sigf((b0 + b1) + (b2 + b3) + fxv);
                    fc += f * g_c[ch * Hv + J];
                }
                __syncwarp();
                *(float4*)&hb[lane * 4]       = make_float4(hr0, hr1, hr2, hr3);
                *(float4*)&hb[128 + lane * 4] = make_float4(hr4, hr5, hr6, hr7);
                __syncwarp();
                float i0 = 0, i1 = 0, i2 = 0, i3 = 0;
                float o0 = 0, o1 = 0, o2 = 0, o3 = 0;
                float u0 = 0, u1 = 0, u2 = 0, u3 = 0;
                #pragma unroll 4
                for (int k = 0; k < Hv; k += 4) {
                    float4 hv = *(const float4*)&hb[k];
                    i0 += hv.x * Wih_sh[(k + 0) * 32 + lane];
                    i1 += hv.y * Wih_sh[(k + 1) * 32 + lane];
                    i2 += hv.z * Wih_sh[(k + 2) * 32 + lane];
                    i3 += hv.w * Wih_sh[(k + 3) * 32 + lane];
                    o0 += hv.x * Woh_sh[(k + 0) * 32 + lane];
                    o1 += hv.y * Woh_sh[(k + 1) * 32 + lane];
                    o2 += hv.z * Woh_sh[(k + 2) * 32 + lane];
                    o3 += hv.w * Woh_sh[(k + 3) * 32 + lane];
                    u0 += hv.x * Wuh_sh[(k + 0) * 32 + lane];
                    u1 += hv.y * Wuh_sh[(k + 1) * 32 + lane];
                    u2 += hv.z * Wuh_sh[(k + 2) * 32 + lane];
                    u3 += hv.w * Wuh_sh[(k + 3) * 32 + lane];
                }
                int nidx = n * Hv + J;
                float iv = sigf(g_proj[0][nidx] + (i0 + i1) + (i2 + i3));
                float ov = sigf(g_proj[2][nidx] + (o0 + o1) + (o2 + o3));
                float uv = tanhf(g_proj[3][nidx] + (u0 + u1) + (u2 + u3));
                float cn = iv * uv + fc;
                g_c[nidx] = cn;
                g_h[nidx] = ov * tanhf(cn);
            }
            grid_bar();
        }
    }

    // ---- P4: max-pool over time + output head ---------------------------
    if (blk < Bv) {
        float* pooled = scratch;   // 256 floats
        const int b = blk;
        float m = -1e30f;
        for (int s = 0; s < Sv; s++) m = fmaxf(m, g_h[(b * Sv + s) * Hv + tid]);
        pooled[tid] = m;
        __syncthreads();
        if (tid < Lv) {
            float s = b_out[tid];
            for (int j = 0; j < Hv; j++) s += pooled[j] * W_out[j * Lv + tid];
            out[b * Lv + tid] = s;
        }
    }
}

// ---------------- launch --------------------------------------------------
extern "C" void kernel_launch(void* const* d_in, const int* in_sizes, int n_in,
                              void* d_out, int out_size) {
    // metadata order: xs, rels, child_idx, parent_idx, node_height, [n_levels],
    // emb_W, rel_W, W_ix, b_ix, W_ih, b_ih, W_fx, b_fx, W_fh, b_fh,
    // W_ox, W_oh, W_ux, W_uh, W_out, b_out
    const int s = (n_in >= 22) ? 1 : 0;   // robust to n_levels scalar presence
    const int* xs          = (const int*)d_in[0];
    const int* rels        = (const int*)d_in[1];
    const int* child_idx   = (const int*)d_in[2];
    const int* parent_idx  = (const int*)d_in[3];
    const int* node_height = (const int*)d_in[4];
    const float* emb_W = (const float*)d_in[5 + s];
    const float* rel_W = (const float*)d_in[6 + s];
    const float* W_ix  = (const float*)d_in[7 + s];
    const float* b_ix  = (const float*)d_in[8 + s];
    const float* W_ih  = (const float*)d_in[9 + s];
    const float* b_ih  = (const float*)d_in[10 + s];
    const float* W_fx  = (const float*)d_in[11 + s];
    const float* b_fx  = (const float*)d_in[12 + s];
    const float* W_fh  = (const float*)d_in[13 + s];
    const float* b_fh  = (const float*)d_in[14 + s];
    const float* W_ox  = (const float*)d_in[15 + s];
    const float* W_oh  = (const float*)d_in[16 + s];
    const float* W_ux  = (const float*)d_in[17 + s];
    const float* W_uh  = (const float*)d_in[18 + s];
    const float* W_out = (const float*)d_in[19 + s];
    const float* b_out = (const float*)d_in[20 + s];
    float* out = (float*)d_out;

    cudaFuncSetAttribute(main_kernel, cudaFuncAttributeMaxDynamicSharedMemorySize, SMEM_BYTES);

    setup_kernel<<<1, 1024>>>(child_idx, parent_idx, node_height);
    main_kernel<<<NCTA, NTHR, SMEM_BYTES>>>(xs, rels, emb_W, rel_W,
                                            W_ix, b_ix, W_ih, b_ih,
                                            W_fx, b_fx, W_fh, b_fh,
                                            W_ox, W_oh, W_ux, W_uh,
                                            W_out, b_out, out);
}

// round 2
// speedup vs baseline: 1.1682x; 1.1682x over previous
#include <cuda_runtime.h>

#define Nn   2048      // B*S
#define Bv   16
#define Sv   128
#define Hv   256
#define DINv 256
#define DEv  192
#define DRv  64
#define Ev   2032      // B*(S-1)
#define Lv   12
#define NCTA 128
#define NTHR 512
#define SMEM_BYTES 196608   // 48K floats: 4x8192 weights + 16384 scratch

// packed fp32x2 FMA (sm_103a FFMA2)
#define FFMA2(acc, a, b) asm("fma.rn.f32x2 %0, %1, %2, %0;" : "+l"(acc) : "l"(a), "l"(b))

__device__ __forceinline__ float pairsum(unsigned long long v) {
    float lo, hi;
    asm("mov.b64 {%0, %1}, %2;" : "=f"(lo), "=f"(hi) : "l"(v));
    return lo + hi;
}

// ---------------- device scratch (no allocations allowed) ----------------
__device__ float g_x[Nn * DINv];
__device__ float g_proj[4][Nn * Hv];   // ix(+b_ix+b_ih), fx(+b_fx+b_fh), ox, ux
__device__ float g_h[Nn * Hv];
__device__ float g_c[Nn * Hv];
__device__ int   g_coff[Nn + 1];
__device__ int   g_children[Ev];
__device__ int   g_lvl_off[34];
__device__ int   g_lvl_nodes[Nn];
__device__ int   g_maxlev;
__device__ unsigned g_bar_cnt = 0;
__device__ unsigned g_bar_gen = 0;

// ---------------- software grid barrier (all 128 CTAs resident) ----------
__device__ __forceinline__ void grid_bar() {
    __syncthreads();
    if (threadIdx.x == 0) {
        __threadfence();                       // release my CTA's writes
        volatile unsigned* genp = (volatile unsigned*)&g_bar_gen;
        unsigned gen = *genp;                  // read phase BEFORE arriving
        unsigned t = atomicAdd(&g_bar_cnt, 1u);
        if (t == gridDim.x - 1) {
            g_bar_cnt = 0;
            __threadfence();
            atomicAdd(&g_bar_gen, 1u);         // release
        } else {
            int it = 0;
            while (*genp == gen) { if (++it > 32) __nanosleep(20); }
        }
        __threadfence();                       // acquire (CCTL.IVALL -> L1 safe)
    }
    __syncthreads();
}

__device__ __forceinline__ float sigf(float x) {
    return 1.0f / (1.0f + __expf(-x));
}

// ---------------- setup: CSR of children + level buckets -----------------
__global__ void setup_kernel(const int* __restrict__ child_idx,
                             const int* __restrict__ parent_idx,
                             const int* __restrict__ node_height) {
    __shared__ int cnt[Nn];
    __shared__ int psm[Ev];
    __shared__ int hsm[Nn];
    __shared__ int part[256];
    __shared__ int lvl[33];
    __shared__ int lfill[33];
    const int tid = threadIdx.x;               // 1024 threads
    for (int i = tid; i < Nn; i += 1024) { cnt[i] = 0; hsm[i] = node_height[i]; }
    for (int i = tid; i < Ev; i += 1024) psm[i] = parent_idx[i];
    if (tid < 33) { lvl[tid] = 0; lfill[tid] = 0; }
    __syncthreads();
    for (int e = tid; e < Ev; e += 1024) atomicAdd(&cnt[psm[e]], 1);
    for (int n = tid; n < Nn; n += 1024) atomicAdd(&lvl[hsm[n]], 1);
    __syncthreads();
    if (tid < 256) { int s = 0; for (int i = 0; i < 8; i++) s += cnt[tid * 8 + i]; part[tid] = s; }
    __syncthreads();
    if (tid == 0) {
        int run = 0;
        for (int i = 0; i < 256; i++) { int v = part[i]; part[i] = run; run += v; }
        int run2 = 0, maxl = 0;
        for (int l = 0; l < 33; l++) {
            g_lvl_off[l] = run2;
            if (lvl[l] > 0) maxl = l;
            run2 += lvl[l];
        }
        g_lvl_off[33] = run2;
        g_maxlev = maxl;
    }
    __syncthreads();
    if (tid < 256) {
        int run = part[tid];
        for (int i = 0; i < 8; i++) { int idx = tid * 8 + i; g_coff[idx] = run; run += cnt[idx]; }
        if (tid == 255) g_coff[Nn] = run;
    }
    __syncthreads();
    // deterministic CSR scatter: rank = #earlier same-parent edges (same batch)
    for (int e = tid; e < Ev; e += 1024) {
        int p = psm[e];
        int bstart = (e / (Sv - 1)) * (Sv - 1);
        int rank = 0;
        for (int e2 = bstart; e2 < e; e2++) rank += (psm[e2] == p);
        g_children[g_coff[p] + rank] = child_idx[e];
    }
    // level bucket fill: order within a level is numerically irrelevant
    for (int n = tid; n < Nn; n += 1024) {
        int lv = hsm[n];
        int r = atomicAdd(&lfill[lv], 1);
        g_lvl_nodes[g_lvl_off[lv] + r] = n;
    }
}

// ---------------- persistent kernel ---------------------------------------
__global__ void __launch_bounds__(NTHR, 1)
main_kernel(const int* __restrict__ xs, const int* __restrict__ rels,
            const float* __restrict__ emb_W, const float* __restrict__ rel_W,
            const float* __restrict__ W_ix, const float* __restrict__ b_ix,
            const float* __restrict__ W_ih, const float* __restrict__ b_ih,
            const float* __restrict__ W_fx, const float* __restrict__ b_fx,
            const float* __restrict__ W_fh, const float* __restrict__ b_fh,
            const float* __restrict__ W_ox, const float* __restrict__ W_oh,
            const float* __restrict__ W_ux, const float* __restrict__ W_uh,
            const float* __restrict__ W_out, const float* __restrict__ b_out,
            float* __restrict__ out) {
    extern __shared__ float sm[];
    // vectorized weight layout: W4[(k>>2)*128 + col*4 + (k&3)]
    float* Wih4 = sm;                 // in P0/P1 this region holds the Wx slice
    float* Woh4 = sm + 8192;
    float* Wuh4 = sm + 16384;
    float* Wfh4 = sm + 24576;
    float* scratch = sm + 32768;      // 16384 floats

    const int tid  = threadIdx.x;
    const int lane = tid & 31;
    const int warp = tid >> 5;
    const int blk  = blockIdx.x;
    const int cgr  = blk & 7;         // recurrence column group (32 cols)
    const int cgp  = blk & 31;        // prologue column group (32 cols of 4H)

    // ---- P0: Wx slice (vectorized) + build x = [emb | rel] --------------
    {
        const float* mats[4] = {W_ix, W_fx, W_ox, W_ux};
        const float* Wsel = mats[cgp >> 3];
        const int jb = (cgp & 7) * 32;
        for (int it = 0; it < 16; it++) {
            int k = it * 16 + (tid >> 5);
            int col = tid & 31;
            Wih4[(k >> 2) * 128 + col * 4 + (k & 3)] = Wsel[k * Hv + jb + col];
        }
        for (int rr = (tid >> 8); rr < 16; rr += 2) {
            int row = blk * 16 + rr;
            int j = tid & 255;
            float v = (j < DEv) ? emb_W[xs[row] * DEv + j]
                                : rel_W[rels[row] * DRv + (j - DEv)];
            g_x[row * DINv + j] = v;
        }
    }
    grid_bar();

    // ---- P1: input projections (FFMA2), biases folded --------------------
    {
        const int mat = cgp >> 3;
        const int jcol = (cgp & 7) * 32 + lane;
        float bias = 0.0f;
        if (mat == 0)      bias = b_ix[jcol] + b_ih[jcol];
        else if (mat == 1) bias = b_fx[jcol] + b_fh[jcol];
        float* x4 = scratch + warp * 1024;     // 4 nodes x 256, node-major
        const int slot = (blk >> 5) * 16 + warp;   // 0..63
        float* dst = g_proj[mat];
        for (int t = 0; t < 8; t++) {
            int nb = slot * 32 + t * 4;
            __syncwarp();
            #pragma unroll
            for (int m = 0; m < 4; m++) {
                const float4* src = (const float4*)(g_x + (nb + m) * DINv);
                float4 a = src[lane], b = src[lane + 32];
                float4* dm = (float4*)(x4 + m * 256);
                dm[lane] = a; dm[lane + 32] = b;
            }
            __syncwarp();
            unsigned long long accA[4] = {0,0,0,0}, accB[4] = {0,0,0,0};
            #pragma unroll 4
            for (int k4 = 0; k4 < 64; k4++) {
                ulonglong2 wv = *(const ulonglong2*)&Wih4[k4 * 128 + lane * 4];
                #pragma unroll
                for (int m = 0; m < 4; m++) {
                    ulonglong2 xv = *(const ulonglong2*)&x4[m * 256 + k4 * 4];
                    FFMA2(accA[m], xv.x, wv.x);
                    FFMA2(accB[m], xv.y, wv.y);
                }
            }
            #pragma unroll
            for (int m = 0; m < 4; m++)
                dst[(nb + m) * Hv + jcol] = pairsum(accA[m]) + pairsum(accB[m]) + bias;
        }
        __syncthreads();     // everyone done with Wx region
        // load recurrent weight slices (vectorized layout)
        const int jb2 = cgr * 32;
        for (int it = 0; it < 16; it++) {
            int k = it * 16 + (tid >> 5);
            int col = tid & 31;
            int didx = (k >> 2) * 128 + col * 4 + (k & 3);
            int sidx = k * Hv + jb2 + col;
            Wih4[didx] = W_ih[sidx];
            Woh4[didx] = W_oh[sidx];
            Wuh4[didx] = W_uh[sidx];
            Wfh4[didx] = W_fh[sidx];
        }
    }
    grid_bar();

    // ---- P2: level 0 (leaves): pure elementwise -------------------------
    {
        int c0 = g_lvl_off[1];
        int tot = c0 * Hv;
        for (int e = blk * NTHR + tid; e < tot; e += NCTA * NTHR) {
            int n = g_lvl_nodes[e >> 8];
            int j = e & 255;
            int idx = n * Hv + j;
            float iv = sigf(g_proj[0][idx]);
            float ov = sigf(g_proj[2][idx]);
            float uv = __tanhf(g_proj[3][idx]);
            float cv = iv * uv;
            g_c[idx] = cv;
            g_h[idx] = ov * __tanhf(cv);
        }
    }
    grid_bar();

    // ---- P3: bottom-up levels (FFMA2 matvecs) ---------------------------
    {
        const int maxlev = g_maxlev;
        float* hb = scratch + warp * 512;
        float* cb = hb + 256;
        const int J = cgr * 32 + lane;
        const int slot = (blk >> 3) * 16 + warp;   // 0..255

        for (int lev = 1; lev <= maxlev; lev++) {
            int base = g_lvl_off[lev];
            int cnt  = g_lvl_off[lev + 1] - base;
            for (int idx = slot; idx < cnt; idx += 256) {
                int n = g_lvl_nodes[base + idx];
                float fxv = g_proj[1][n * Hv + J];
                int cs = g_coff[n], ce = g_coff[n + 1];
                float4 s0 = make_float4(0,0,0,0), s1 = make_float4(0,0,0,0);
                float fc = 0.0f;
                for (int ci = cs; ci < ce; ci++) {
                    int ch = g_children[ci];
                    __syncwarp();
                    const float4* hsrc = (const float4*)(g_h + ch * Hv);
                    float4 v0 = hsrc[lane], v1 = hsrc[lane + 32];
                    float4* cbv = (float4*)cb;
                    cbv[lane] = v0; cbv[lane + 32] = v1;
                    s0.x += v0.x; s0.y += v0.y; s0.z += v0.z; s0.w += v0.w;
                    s1.x += v1.x; s1.y += v1.y; s1.z += v1.z; s1.w += v1.w;
                    __syncwarp();
                    unsigned long long fA = 0, fB = 0;
                    #pragma unroll 8
                    for (int k4 = 0; k4 < 64; k4++) {
                        ulonglong2 cv = *(const ulonglong2*)&cb[k4 * 4];
                        ulonglong2 wf = *(const ulonglong2*)&Wfh4[k4 * 128 + lane * 4];
                        FFMA2(fA, cv.x, wf.x);
                        FFMA2(fB, cv.y, wf.y);
                    }
                    float f = sigf(pairsum(fA) + pairsum(fB) + fxv);
                    fc += f * g_c[ch * Hv + J];
                }
                __syncwarp();
                float4* hbv = (float4*)hb;
                hbv[lane] = s0; hbv[lane + 32] = s1;
                __syncwarp();
                unsigned long long iA = 0, iB = 0, oA = 0, oB = 0, uA = 0, uB = 0;
                #pragma unroll 4
                for (int k4 = 0; k4 < 64; k4++) {
                    ulonglong2 hv = *(const ulonglong2*)&hb[k4 * 4];
                    ulonglong2 wi = *(const ulonglong2*)&Wih4[k4 * 128 + lane * 4];
                    ulonglong2 wo = *(const ulonglong2*)&Woh4[k4 * 128 + lane * 4];
                    ulonglong2 wu = *(const ulonglong2*)&Wuh4[k4 * 128 + lane * 4];
                    FFMA2(iA, hv.x, wi.x); FFMA2(iB, hv.y, wi.y);
                    FFMA2(oA, hv.x, wo.x); FFMA2(oB, hv.y, wo.y);
                    FFMA2(uA, hv.x, wu.x); FFMA2(uB, hv.y, wu.y);
                }
                int nidx = n * Hv + J;
                float iv = sigf(g_proj[0][nidx] + pairsum(iA) + pairsum(iB));
                float ov = sigf(g_proj[2][nidx] + pairsum(oA) + pairsum(oB));
                float uv = __tanhf(g_proj[3][nidx] + pairsum(uA) + pairsum(uB));
                float cn = iv * uv + fc;
                g_c[nidx] = cn;
                g_h[nidx] = ov * __tanhf(cn);
            }
            grid_bar();
        }
    }

    // ---- P4: max-pool over time + output head ---------------------------
    if (blk < Bv) {
        float* pooled = scratch;       // 512 floats
        const int b = blk;
        const int col = tid & 255, half = tid >> 8;
        float m = -1e30f;
        for (int s = half; s < Sv; s += 2)
            m = fmaxf(m, g_h[(b * Sv + s) * Hv + col]);
        pooled[half * 256 + col] = m;
        __syncthreads();
        if (tid < Hv) pooled[tid] = fmaxf(pooled[tid], pooled[tid + 256]);
        __syncthreads();
        if (tid < Lv) {
            float sacc = b_out[tid];
            for (int j = 0; j < Hv; j++) sacc += pooled[j] * W_out[j * Lv + tid];
            out[b * Lv + tid] = sacc;
        }
    }
}

// ---------------- launch --------------------------------------------------
extern "C" void kernel_launch(void* const* d_in, const int* in_sizes, int n_in,
                              void* d_out, int out_size) {
    const int s = (n_in >= 22) ? 1 : 0;   // robust to n_levels scalar presence
    const int* xs          = (const int*)d_in[0];
    const int* rels        = (const int*)d_in[1];
    const int* child_idx   = (const int*)d_in[2];
    const int* parent_idx  = (const int*)d_in[3];
    const int* node_height = (const int*)d_in[4];
    const float* emb_W = (const float*)d_in[5 + s];
    const float* rel_W = (const float*)d_in[6 + s];
    const float* W_ix  = (const float*)d_in[7 + s];
    const float* b_ix  = (const float*)d_in[8 + s];
    const float* W_ih  = (const float*)d_in[9 + s];
    const float* b_ih  = (const float*)d_in[10 + s];
    const float* W_fx  = (const float*)d_in[11 + s];
    const float* b_fx  = (const float*)d_in[12 + s];
    const float* W_fh  = (const float*)d_in[13 + s];
    const float* b_fh  = (const float*)d_in[14 + s];
    const float* W_ox  = (const float*)d_in[15 + s];
    const float* W_oh  = (const float*)d_in[16 + s];
    const float* W_ux  = (const float*)d_in[17 + s];
    const float* W_uh  = (const float*)d_in[18 + s];
    const float* W_out = (const float*)d_in[19 + s];
    const float* b_out = (const float*)d_in[20 + s];
    float* out = (float*)d_out;

    cudaFuncSetAttribute(main_kernel, cudaFuncAttributeMaxDynamicSharedMemorySize, SMEM_BYTES);

    setup_kernel<<<1, 1024>>>(child_idx, parent_idx, node_height);
    main_kernel<<<NCTA, NTHR, SMEM_BYTES>>>(xs, rels, emb_W, rel_W,
                                            W_ix, b_ix, W_ih, b_ih,
                                            W_fx, b_fx, W_fh, b_fh,
                                            W_ox, W_oh, W_ux, W_uh,
                                            W_out, b_out, out);
}

// round 3
// speedup vs baseline: 1.7968x; 1.5381x over previous
#include <cuda_runtime.h>

#define Nn   2048      // B*S
#define Bv   16
#define Sv   128
#define Hv   256
#define DINv 256
#define DEv  192
#define DRv  64
#define Ev   2032      // B*(S-1)
#define Lv   12
#define NCTA 128       // 16 trees x 8 column groups
#define NTHR 512
#define SMEM_BYTES 196608   // 48K floats: 32K weights + 16K scratch

// packed fp32x2 FMA (sm_103a FFMA2)
#define FFMA2(acc, a, b) asm("fma.rn.f32x2 %0, %1, %2, %0;" : "+l"(acc) : "l"(a), "l"(b))

__device__ __forceinline__ float pairsum(unsigned long long v) {
    float lo, hi;
    asm("mov.b64 {%0, %1}, %2;" : "=f"(lo), "=f"(hi) : "l"(v));
    return lo + hi;
}

// ---------------- device scratch (no allocations allowed) ----------------
__device__ float g_proj[4][Nn * Hv];   // ix(+b_ix+b_ih), fx(+b_fx+b_fh), ox, ux
__device__ float g_h[Nn * Hv];
__device__ float g_c[Nn * Hv];
__device__ float g_pooled[Bv * Hv];
__device__ int   g_coff[Nn + 1];
__device__ int   g_children[Ev];
__device__ int   g_tl_off[512];        // [16][32] per-tree level offsets
__device__ int   g_tl_nodes[Nn];       // per-tree level-bucketed node ids
__device__ int   g_tmax[Bv];
__device__ unsigned g_tcnt[Bv * 32];   // per-tree barrier, 128B apart
__device__ unsigned g_tgen[Bv * 32];

// ---------------- per-tree barrier (8 CTAs) -------------------------------
__device__ __forceinline__ void tree_bar(int b) {
    __syncthreads();
    if (threadIdx.x == 0) {
        __threadfence();                        // release this CTA's writes
        volatile unsigned* genp = (volatile unsigned*)&g_tgen[b * 32];
        unsigned gen = *genp;                   // snapshot BEFORE arriving
        if (atomicAdd(&g_tcnt[b * 32], 1u) == 7u) {
            atomicExch(&g_tcnt[b * 32], 0u);
            __threadfence();
            atomicAdd(&g_tgen[b * 32], 1u);     // release
        } else {
            int it = 0;
            while (*genp == gen) { if (++it > 64) __nanosleep(40); }
        }
        __threadfence();                        // acquire
    }
    __syncthreads();
}

__device__ __forceinline__ float sigf(float x) {
    return 1.0f / (1.0f + __expf(-x));
}

// ---------------- setup: CSR of children + per-tree level buckets ---------
__global__ void setup_kernel(const int* __restrict__ child_idx,
                             const int* __restrict__ parent_idx,
                             const int* __restrict__ node_height) {
    __shared__ int cnt[Nn];
    __shared__ int psm[Ev];
    __shared__ int hsm[Nn];
    __shared__ int part[256];
    __shared__ int lvl[512];
    __shared__ int lfill[512];
    __shared__ int loff[512];
    const int tid = threadIdx.x;               // 1024 threads
    for (int i = tid; i < Nn; i += 1024) { cnt[i] = 0; hsm[i] = node_height[i]; }
    for (int i = tid; i < Ev; i += 1024) psm[i] = parent_idx[i];
    for (int i = tid; i < 512; i += 1024) { lvl[i] = 0; lfill[i] = 0; }
    __syncthreads();
    for (int e = tid; e < Ev; e += 1024) atomicAdd(&cnt[psm[e]], 1);
    for (int n = tid; n < Nn; n += 1024) atomicAdd(&lvl[(n >> 7) * 32 + hsm[n]], 1);
    __syncthreads();
    if (tid < 256) { int s = 0; for (int i = 0; i < 8; i++) s += cnt[tid * 8 + i]; part[tid] = s; }
    __syncthreads();
    if (tid == 0) {
        int run = 0;
        for (int i = 0; i < 256; i++) { int v = part[i]; part[i] = run; run += v; }
    }
    if (tid < 16) {                            // per-tree level prefix + maxlev
        int run = 0, mx = 1;
        for (int l = 0; l < 32; l++) {
            loff[tid * 32 + l] = tid * 128 + run;
            if (lvl[tid * 32 + l] > 0) mx = l;
            run += lvl[tid * 32 + l];
        }
        g_tmax[tid] = mx;
    }
    __syncthreads();
    for (int i = tid; i < 512; i += 1024) g_tl_off[i] = loff[i];
    if (tid < 256) {
        int run = part[tid];
        for (int i = 0; i < 8; i++) { int idx = tid * 8 + i; g_coff[idx] = run; run += cnt[idx]; }
        if (tid == 255) g_coff[Nn] = run;
    }
    __syncthreads();
    // deterministic CSR scatter: rank = #earlier same-parent edges (same batch)
    for (int e = tid; e < Ev; e += 1024) {
        int p = psm[e];
        int bstart = (e / (Sv - 1)) * (Sv - 1);
        int rank = 0;
        for (int e2 = bstart; e2 < e; e2++) rank += (psm[e2] == p);
        g_children[g_coff[p] + rank] = child_idx[e];
    }
    // per-tree level bucket fill (intra-level order numerically irrelevant)
    for (int n = tid; n < Nn; n += 1024) {
        int key = (n >> 7) * 32 + hsm[n];
        int r = atomicAdd(&lfill[key], 1);
        g_tl_nodes[loff[key] + r] = n;
    }
}

// ---------------- persistent kernel: fully per-tree asynchronous ----------
__global__ void __launch_bounds__(NTHR, 1)
main_kernel(const int* __restrict__ xs, const int* __restrict__ rels,
            const float* __restrict__ emb_W, const float* __restrict__ rel_W,
            const float* __restrict__ W_ix, const float* __restrict__ b_ix,
            const float* __restrict__ W_ih, const float* __restrict__ b_ih,
            const float* __restrict__ W_fx, const float* __restrict__ b_fx,
            const float* __restrict__ W_fh, const float* __restrict__ b_fh,
            const float* __restrict__ W_ox, const float* __restrict__ W_oh,
            const float* __restrict__ W_ux, const float* __restrict__ W_uh,
            const float* __restrict__ W_out, const float* __restrict__ b_out,
            float* __restrict__ out) {
    extern __shared__ float sm[];
    // P1: sm[0..32768) = 256x128 input-weight slice, layout [k/4][c*4 + k%4]
    // P3: same region re-used as 4 recurrent 256x32 slices
    float* Wih4 = sm;
    float* Woh4 = sm + 8192;
    float* Wuh4 = sm + 16384;
    float* Wfh4 = sm + 24576;
    float* scratch = sm + 32768;      // 16384 floats

    const int tid  = threadIdx.x;
    const int lane = tid & 31;
    const int warp = tid >> 5;
    const int blk  = blockIdx.x;
    const int b    = blk >> 3;        // tree id
    const int g    = blk & 7;         // column group

    // ---- P1: input projections for this tree's 128 nodes, cols [g*128,+128)
    {
        const float* mats[4] = {W_ix, W_fx, W_ox, W_ux};
        const float* Wsel = mats[g >> 1];
        const int colbase = (g & 1) * 128;
        float* Wsm = sm;
        for (int idx = tid; idx < 32768; idx += NTHR) {
            int k = idx >> 7, c = idx & 127;
            Wsm[(k >> 2) * 512 + c * 4 + (k & 3)] = Wsel[k * Hv + colbase + c];
        }
        __syncthreads();
        const int matid = g >> 1;
        float* dst = g_proj[matid];
        float* x4 = scratch + warp * 1024;
        for (int t = 0; t < 2; t++) {
            int ng = warp * 2 + t;              // 0..31 node groups of 4
            int nb = b * Sv + ng * 4;           // global node base
            __syncwarp();
            #pragma unroll
            for (int m = 0; m < 4; m++) {
                int n = nb + m;
                const float4* er = (const float4*)(emb_W + (size_t)xs[n] * DEv);
                const float4* rr = (const float4*)(rel_W + (size_t)rels[n] * DRv);
                float4 a = er[lane];
                float4 bb = (lane < 16) ? er[lane + 32] : rr[lane - 16];
                float4* dm = (float4*)(x4 + m * 256);
                dm[lane] = a; dm[lane + 32] = bb;
            }
            __syncwarp();
            for (int cg = 0; cg < 4; cg++) {
                unsigned long long accA[4] = {0,0,0,0}, accB[4] = {0,0,0,0};
                const float* wp = Wsm + (cg * 32 + lane) * 4;
                #pragma unroll 4
                for (int k4 = 0; k4 < 64; k4++) {
                    ulonglong2 wv = *(const ulonglong2*)(wp + k4 * 512);
                    #pragma unroll
                    for (int m = 0; m < 4; m++) {
                        ulonglong2 xv = *(const ulonglong2*)&x4[m * 256 + k4 * 4];
                        FFMA2(accA[m], xv.x, wv.x);
                        FFMA2(accB[m], xv.y, wv.y);
                    }
                }
                int colm = colbase + cg * 32 + lane;
                float bias = 0.0f;
                if (matid == 0)      bias = b_ix[colm] + b_ih[colm];
                else if (matid == 1) bias = b_fx[colm] + b_fh[colm];
                #pragma unroll
                for (int m = 0; m < 4; m++)
                    dst[(size_t)(nb + m) * Hv + colm] =
                        pairsum(accA[m]) + pairsum(accB[m]) + bias;
            }
        }
        __syncthreads();
        // load recurrent weight slices (overwrite Wsm region)
        const int jb2 = g * 32;
        for (int it = 0; it < 16; it++) {
            int k = it * 16 + (tid >> 5);
            int col = tid & 31;
            int didx = (k >> 2) * 128 + col * 4 + (k & 3);
            int sidx = k * Hv + jb2 + col;
            Wih4[didx] = W_ih[sidx];
            Woh4[didx] = W_oh[sidx];
            Wuh4[didx] = W_uh[sidx];
            Wfh4[didx] = W_fh[sidx];
        }
    }
    tree_bar(b);

    // ---- P2: level 0 (leaves): pure elementwise, split over 8 CTAs -------
    {
        int base0 = g_tl_off[b * 32];
        int cnt0  = g_tl_off[b * 32 + 1] - base0;
        int tot = cnt0 * Hv;
        for (int e = g * NTHR + tid; e < tot; e += 8 * NTHR) {
            int n = g_tl_nodes[base0 + (e >> 8)];
            int j = e & 255;
            size_t idx = (size_t)n * Hv + j;
            float iv = sigf(g_proj[0][idx]);
            float ov = sigf(g_proj[2][idx]);
            float uv = __tanhf(g_proj[3][idx]);
            float cv = iv * uv;
            g_c[idx] = cv;
            g_h[idx] = ov * __tanhf(cv);
        }
    }
    tree_bar(b);

    // ---- P3: bottom-up levels of THIS tree only ---------------------------
    {
        const int tmax = g_tmax[b];
        float* hb = scratch + warp * 512;
        float* cb = hb + 256;
        const int J = g * 32 + lane;

        for (int lev = 1; lev <= tmax; lev++) {
            int base = g_tl_off[b * 32 + lev];
            int cnt  = g_tl_off[b * 32 + lev + 1] - base;
            for (int idx = warp; idx < cnt; idx += 16) {
                int n = g_tl_nodes[base + idx];
                float fxv = g_proj[1][(size_t)n * Hv + J];
                int cs = g_coff[n], ce = g_coff[n + 1];
                float4 s0 = make_float4(0,0,0,0), s1 = make_float4(0,0,0,0);
                float fc = 0.0f;
                for (int ci = cs; ci < ce; ci++) {
                    int ch = g_children[ci];
                    __syncwarp();
                    const float4* hsrc = (const float4*)(g_h + (size_t)ch * Hv);
                    float4 v0 = hsrc[lane], v1 = hsrc[lane + 32];
                    float4* cbv = (float4*)cb;
                    cbv[lane] = v0; cbv[lane + 32] = v1;
                    s0.x += v0.x; s0.y += v0.y; s0.z += v0.z; s0.w += v0.w;
                    s1.x += v1.x; s1.y += v1.y; s1.z += v1.z; s1.w += v1.w;
                    __syncwarp();
                    unsigned long long fA = 0, fB = 0, fC = 0, fD = 0;
                    #pragma unroll 8
                    for (int k4 = 0; k4 < 64; k4 += 2) {
                        ulonglong2 cv0 = *(const ulonglong2*)&cb[k4 * 4];
                        ulonglong2 wf0 = *(const ulonglong2*)&Wfh4[k4 * 128 + lane * 4];
                        ulonglong2 cv1 = *(const ulonglong2*)&cb[k4 * 4 + 4];
                        ulonglong2 wf1 = *(const ulonglong2*)&Wfh4[k4 * 128 + 128 + lane * 4];
                        FFMA2(fA, cv0.x, wf0.x);
                        FFMA2(fB, cv0.y, wf0.y);
                        FFMA2(fC, cv1.x, wf1.x);
                        FFMA2(fD, cv1.y, wf1.y);
                    }
                    float f = sigf((pairsum(fA) + pairsum(fB)) +
                                   (pairsum(fC) + pairsum(fD)) + fxv);
                    fc += f * g_c[(size_t)ch * Hv + J];
                }
                __syncwarp();
                float4* hbv = (float4*)hb;
                hbv[lane] = s0; hbv[lane + 32] = s1;
                __syncwarp();
                unsigned long long iA = 0, iB = 0, oA = 0, oB = 0, uA = 0, uB = 0;
                #pragma unroll 4
                for (int k4 = 0; k4 < 64; k4++) {
                    ulonglong2 hv = *(const ulonglong2*)&hb[k4 * 4];
                    ulonglong2 wi = *(const ulonglong2*)&Wih4[k4 * 128 + lane * 4];
                    ulonglong2 wo = *(const ulonglong2*)&Woh4[k4 * 128 + lane * 4];
                    ulonglong2 wu = *(const ulonglong2*)&Wuh4[k4 * 128 + lane * 4];
                    FFMA2(iA, hv.x, wi.x); FFMA2(iB, hv.y, wi.y);
                    FFMA2(oA, hv.x, wo.x); FFMA2(oB, hv.y, wo.y);
                    FFMA2(uA, hv.x, wu.x); FFMA2(uB, hv.y, wu.y);
                }
                size_t nidx = (size_t)n * Hv + J;
                float iv = sigf(g_proj[0][nidx] + pairsum(iA) + pairsum(iB));
                float ov = sigf(g_proj[2][nidx] + pairsum(oA) + pairsum(oB));
                float uv = __tanhf(g_proj[3][nidx] + pairsum(uA) + pairsum(uB));
                float cn = iv * uv + fc;
                g_c[nidx] = cn;
                g_h[nidx] = ov * __tanhf(cn);
            }
            tree_bar(b);
        }
    }

    // ---- P4: per-tree max-pool + output head ------------------------------
    {
        // this CTA pools its 32 columns over the 128 time steps
        int col = g * 32 + lane;
        int srow = warp;                         // 16 warps x 8 steps
        float m = -1e30f;
        for (int s = srow; s < Sv; s += 16)
            m = fmaxf(m, g_h[(size_t)(b * Sv + s) * Hv + col]);
        scratch[warp * 32 + lane] = m;
        __syncthreads();
        if (tid < 32) {
            float mm = scratch[tid];
            #pragma unroll
            for (int r = 1; r < 16; r++) mm = fmaxf(mm, scratch[r * 32 + tid]);
            g_pooled[b * Hv + g * 32 + tid] = mm;
        }
    }
    tree_bar(b);
    if (g == 0 && warp < Lv) {
        float acc = 0.0f;
        for (int k = lane; k < Hv; k += 32)
            acc += g_pooled[b * Hv + k] * W_out[k * Lv + warp];
        #pragma unroll
        for (int off = 16; off; off >>= 1)
            acc += __shfl_down_sync(0xFFFFFFFFu, acc, off);
        if (lane == 0) out[b * Lv + warp] = acc + b_out[warp];
    }
}

// ---------------- launch --------------------------------------------------
extern "C" void kernel_launch(void* const* d_in, const int* in_sizes, int n_in,
                              void* d_out, int out_size) {
    const int s = (n_in >= 22) ? 1 : 0;   // robust to n_levels scalar presence
    const int* xs          = (const int*)d_in[0];
    const int* rels        = (const int*)d_in[1];
    const int* child_idx   = (const int*)d_in[2];
    const int* parent_idx  = (const int*)d_in[3];
    const int* node_height = (const int*)d_in[4];
    const float* emb_W = (const float*)d_in[5 + s];
    const float* rel_W = (const float*)d_in[6 + s];
    const float* W_ix  = (const float*)d_in[7 + s];
    const float* b_ix  = (const float*)d_in[8 + s];
    const float* W_ih  = (const float*)d_in[9 + s];
    const float* b_ih  = (const float*)d_in[10 + s];
    const float* W_fx  = (const float*)d_in[11 + s];
    const float* b_fx  = (const float*)d_in[12 + s];
    const float* W_fh  = (const float*)d_in[13 + s];
    const float* b_fh  = (const float*)d_in[14 + s];
    const float* W_ox  = (const float*)d_in[15 + s];
    const float* W_oh  = (const float*)d_in[16 + s];
    const float* W_ux  = (const float*)d_in[17 + s];
    const float* W_uh  = (const float*)d_in[18 + s];
    const float* W_out = (const float*)d_in[19 + s];
    const float* b_out = (const float*)d_in[20 + s];
    float* out = (float*)d_out;

    cudaFuncSetAttribute(main_kernel, cudaFuncAttributeMaxDynamicSharedMemorySize, SMEM_BYTES);

    setup_kernel<<<1, 1024>>>(child_idx, parent_idx, node_height);
    main_kernel<<<NCTA, NTHR, SMEM_BYTES>>>(xs, rels, emb_W, rel_W,
                                            W_ix, b_ix, W_ih, b_ih,
                                            W_fx, b_fx, W_fh, b_fh,
                                            W_ox, W_oh, W_ux, W_uh,
                                            W_out, b_out, out);
}